// round 10
// baseline (speedup 1.0000x reference)
#include <cuda_runtime.h>
#include <cuda_bf16.h>
#include <cstdint>

#define B    64
#define HDIM 1024
#define VDIM 23262
#define EDIM 300
#define G4   4096
#define KCAT (HDIM + EDIM)

#define CTX_OFF   1048576
#define GATES_OFF 2097152

typedef unsigned long long ull;

// ---------------- scratch ----------------
__device__ float g_pm[B * 64];
__device__ float g_pl[B * 64];
__device__ float g_pacc[(size_t)B * 64 * HDIM];
__device__ float g_ctxc[B * HDIM];
__device__ float g_ctxh[B * HDIM];
__device__ float g_pctx[B * HDIM];
__device__ float g_pgates[B * G4];
__device__ float g_hN[B * HDIM];
__device__ float g_part[(size_t)4 * 1024 * 1024];
__device__ int g_ctr;
__device__ int g_bar_cnt;
__device__ volatile int g_bar_gen;

// ---------------- fp32x2 helpers ----------------
__device__ __forceinline__ void ffma2(ull& d, ull a, ull w) {
    asm("fma.rn.f32x2 %0, %1, %2, %0;" : "+l"(d) : "l"(a), "l"(w));
}
__device__ __forceinline__ ull pack_dup(float x) {
    ull r; asm("mov.b64 %0, {%1, %1};" : "=l"(r) : "f"(x)); return r;
}
__device__ __forceinline__ float2 unpack2(ull v) {
    float2 r; asm("mov.b64 {%0, %1}, %2;" : "=f"(r.x), "=f"(r.y) : "l"(v)); return r;
}

// ---------------- HMMA helpers ----------------
__device__ __forceinline__ uint32_t swzf(uint32_t o) { return o ^ ((o >> 3) & 0x70); }

__device__ __forceinline__ void cvt16(const float* v, uint32_t* h, uint32_t* l) {
#pragma unroll
    for (int j = 0; j < 8; j++) {
        uint32_t u0 = __float_as_uint(v[2 * j]);
        uint32_t u1 = __float_as_uint(v[2 * j + 1]);
        asm("prmt.b32 %0, %1, %2, 0x7632;" : "=r"(h[j]) : "r"(u0), "r"(u1));
        float l0 = v[2 * j]     - __uint_as_float(u0 & 0xFFFF0000u);
        float l1 = v[2 * j + 1] - __uint_as_float(u1 & 0xFFFF0000u);
        asm("cvt.rn.bf16x2.f32 %0, %1, %2;" : "=r"(l[j]) : "f"(l1), "f"(l0));
    }
}
__device__ __forceinline__ void ldsm4(uint32_t& r0, uint32_t& r1, uint32_t& r2, uint32_t& r3,
                                      uint32_t addr) {
    asm volatile("ldmatrix.sync.aligned.m8n8.x4.shared.b16 {%0,%1,%2,%3}, [%4];"
                 : "=r"(r0), "=r"(r1), "=r"(r2), "=r"(r3) : "r"(addr));
}
__device__ __forceinline__ void hmma(float* c, const uint32_t* a, const uint32_t* b) {
    asm volatile("mma.sync.aligned.m16n8k16.row.col.f32.bf16.bf16.f32 "
                 "{%0,%1,%2,%3}, {%4,%5,%6,%7}, {%8,%9}, {%0,%1,%2,%3};"
                 : "+f"(c[0]), "+f"(c[1]), "+f"(c[2]), "+f"(c[3])
                 : "r"(a[0]), "r"(a[1]), "r"(a[2]), "r"(a[3]), "r"(b[0]), "r"(b[1]));
}
__device__ __forceinline__ void cpasync16(uint32_t dst, const void* src, int szbytes) {
    asm volatile("cp.async.cg.shared.global [%0], [%1], 16, %2;"
                 :: "r"(dst), "l"(src), "r"(szbytes) : "memory");
}

// ---------------- grid-wide barrier (persistent, replay-safe) ----------------
__device__ __forceinline__ void gridbar(int nb) {
    __syncthreads();
    if (threadIdx.x == 0) {
        __threadfence();
        int gen = g_bar_gen;
        if (atomicAdd(&g_bar_cnt, 1) == nb - 1) {
            g_bar_cnt = 0;
            __threadfence();
            g_bar_gen = gen + 1;
        } else {
            while (g_bar_gen == gen) __nanosleep(64);
            __threadfence();
        }
    }
    __syncthreads();
}

// ================= hmma bf16-split GEMM unit =================
template <bool DIRECT>
__device__ __forceinline__ void gemm_unit(
    const float* __restrict__ A, int K,
    const float* __restrict__ W, int ldw,
    int n0, int cs, int ce, int N,
    float* __restrict__ dst, int ldc, const float* __restrict__ bias,
    char* sm)
{
    int tid = threadIdx.x, wid = tid >> 5, lane = tid & 31;
    int g = lane >> 2, tig = lane & 3;
    int mbase = (wid >> 1) * 16, nbase = (wid & 1) * 32;
    uint32_t smb = (uint32_t)__cvta_generic_to_shared(sm);
    int frow = tid >> 2, fqd = tid & 3;

    int la = lane & 7, lb3 = (lane >> 3) & 1, lb4 = (lane >> 4) & 1;
    uint32_t rawA  = (uint32_t)(mbase + la + lb3 * 8) * 128 + (uint32_t)lb4 * 16;
    uint32_t xorA  = (rawA >> 3) & 0x70;
    uint32_t rawB0 = (uint32_t)(nbase + la + lb4 * 8) * 128 + (uint32_t)lb3 * 16;
    uint32_t rawB1 = rawB0 + 2048;
    uint32_t xorB0 = (rawB0 >> 3) & 0x70;
    uint32_t xorB1 = (rawB1 >> 3) & 0x70;
    uint32_t so0 = swzf((uint32_t)frow * 128 + (uint32_t)fqd * 32);
    uint32_t so1 = so0 ^ 16;

    float acc[4][4];
#pragma unroll
    for (int nf = 0; nf < 4; nf++)
#pragma unroll
        for (int j = 0; j < 4; j++) acc[nf][j] = 0.f;

    auto issue = [&](int kc, int buf) {
        int k0 = kc * 64 + fqd * 16;
        uint32_t da = smb + (uint32_t)buf * 32768 + (uint32_t)frow * 256 + (uint32_t)fqd * 64;
        const float* pA = A + (size_t)frow * K + k0;
#pragma unroll
        for (int q = 0; q < 4; q++) cpasync16(da + q * 16, pA + q * 4, 16);
        bool rv = (n0 + frow) < N;
        const float* pW = W + (size_t)(rv ? (n0 + frow) : 0) * ldw + k0;
        uint32_t dw = da + 16384;
#pragma unroll
        for (int q = 0; q < 4; q++) cpasync16(dw + q * 16, pW + q * 4, rv ? 16 : 0);
        asm volatile("cp.async.commit_group;" ::: "memory");
    };

    auto convertbuf = [&](int buf) {
        char* rb = sm + buf * 32768;
        float v[16];
        uint32_t h[8], l[8];
#pragma unroll
        for (int half = 0; half < 2; half++) {
            const float4* r4 = (const float4*)(rb + half * 16384 + frow * 256 + fqd * 64);
            float4 a = r4[0], b4 = r4[1], c4 = r4[2], d4 = r4[3];
            v[0]=a.x; v[1]=a.y; v[2]=a.z; v[3]=a.w;
            v[4]=b4.x; v[5]=b4.y; v[6]=b4.z; v[7]=b4.w;
            v[8]=c4.x; v[9]=c4.y; v[10]=c4.z; v[11]=c4.w;
            v[12]=d4.x; v[13]=d4.y; v[14]=d4.z; v[15]=d4.w;
            cvt16(v, h, l);
            char* d = sm + 65536 + half * 16384;
            *(uint4*)(d + so0)        = make_uint4(h[0], h[1], h[2], h[3]);
            *(uint4*)(d + so1)        = make_uint4(h[4], h[5], h[6], h[7]);
            *(uint4*)(d + 8192 + so0) = make_uint4(l[0], l[1], l[2], l[3]);
            *(uint4*)(d + 8192 + so1) = make_uint4(l[4], l[5], l[6], l[7]);
        }
    };

    if (cs < ce) issue(cs, 0);
    uint32_t bfA = smb + 65536, bfW = smb + 81920;

    for (int ci = cs; ci < ce; ci++) {
        int buf = (ci - cs) & 1;
        asm volatile("cp.async.wait_group 0;" ::: "memory");
        __syncthreads();
        convertbuf(buf);
        if (ci + 1 < ce) issue(ci + 1, buf ^ 1);
        __syncthreads();

#pragma unroll
        for (int ks = 0; ks < 4; ks++) {
            uint32_t kb = (uint32_t)ks * 32;
            uint32_t aA = bfA + ((rawA + kb) ^ xorA);
            uint32_t ah[4], al[4];
            ldsm4(ah[0], ah[1], ah[2], ah[3], aA);
            ldsm4(al[0], al[1], al[2], al[3], aA + 8192);
            uint32_t b0 = bfW + ((rawB0 + kb) ^ xorB0);
            uint32_t b1 = bfW + ((rawB1 + kb) ^ xorB1);
            uint32_t bh[8], bl[8];
            ldsm4(bh[0], bh[1], bh[2], bh[3], b0);
            ldsm4(bh[4], bh[5], bh[6], bh[7], b1);
            ldsm4(bl[0], bl[1], bl[2], bl[3], b0 + 8192);
            ldsm4(bl[4], bl[5], bl[6], bl[7], b1 + 8192);
#pragma unroll
            for (int nf = 0; nf < 4; nf++) {
                hmma(acc[nf], ah, &bh[nf * 2]);
                hmma(acc[nf], ah, &bl[nf * 2]);
                hmma(acc[nf], al, &bh[nf * 2]);
            }
        }
    }

#pragma unroll
    for (int nf = 0; nf < 4; nf++) {
        int row = mbase + g;
        int n   = n0 + nbase + nf * 8 + tig * 2;
        float2 v0 = make_float2(acc[nf][0], acc[nf][1]);
        float2 v1 = make_float2(acc[nf][2], acc[nf][3]);
        if (n < N) {
            if (DIRECT) {
                if (bias) { v0.x += bias[n]; v0.y += bias[n + 1];
                            v1.x += bias[n]; v1.y += bias[n + 1]; }
                *(float2*)&dst[(size_t)row * ldc + n]       = v0;
                *(float2*)&dst[(size_t)(row + 8) * ldc + n] = v1;
            } else {
                *(float2*)&dst[(size_t)row * N + n]       = v0;
                *(float2*)&dst[(size_t)(row + 8) * N + n] = v1;
            }
        }
    }
}

// ================= uber kernel =================
__global__ __launch_bounds__(256, 2) void k_uber(
    const float* __restrict__ enc,
    const int* __restrict__ tokens, const float* __restrict__ emb,
    const float* __restrict__ h0, const float* __restrict__ c0,
    const float* __restrict__ W_in, const float* __restrict__ W_out,
    const float* __restrict__ W_ih, const float* __restrict__ W_hh,
    const float* __restrict__ b_ih, const float* __restrict__ b_hh,
    const float* __restrict__ W_gen, const float* __restrict__ b_gen,
    float* __restrict__ out)
{
    extern __shared__ char sm[];
    __shared__ float4 sq[256];
    __shared__ int s_u;
    int cta = blockIdx.x, tid = threadIdx.x, nb = gridDim.x;
    int tx = tid & 31, ty = tid >> 5;

    float (*sW)[128] = (float(*)[128])sm;
    float (*sA)[64]  = (float(*)[64])(sm + 16384);

    auto mmastep = [&](ull (*acc)[2]) {
#pragma unroll 8
        for (int kk = 0; kk < 32; kk++) {
            float4 a0 = *(const float4*)&sA[kk][ty * 8];
            float4 a1 = *(const float4*)&sA[kk][ty * 8 + 4];
            const ull* wp2 = (const ull*)&sW[kk][tx * 4];
            ull w0 = wp2[0], w1 = wp2[1];
            ull ad[8];
            ad[0] = pack_dup(a0.x); ad[1] = pack_dup(a0.y);
            ad[2] = pack_dup(a0.z); ad[3] = pack_dup(a0.w);
            ad[4] = pack_dup(a1.x); ad[5] = pack_dup(a1.y);
            ad[6] = pack_dup(a1.z); ad[7] = pack_dup(a1.w);
#pragma unroll
            for (int j = 0; j < 8; j++) { ffma2(acc[j][0], ad[j], w0); ffma2(acc[j][1], ad[j], w1); }
        }
    };

    // ---------- P0: q partials = h0 @ W_in, 64 units (8 n-tiles x 8 k-slices) ----------
    if (cta < 64) {
        int n0 = (cta & 7) * 128;
        int slice = cta >> 3;
        ull acc[8][2];
#pragma unroll
        for (int j = 0; j < 8; j++) { acc[j][0] = 0ULL; acc[j][1] = 0ULL; }
        int k0s = slice * 128;
        for (int k0 = k0s; k0 < k0s + 128; k0 += 32) {
            {
                int bb = tid >> 2, kq = (tid & 3) * 4;
                const float* ap = h0 + (size_t)bb * HDIM + k0;
#pragma unroll
                for (int c = 0; c < 2; c++) {
                    int off = kq + c * 16;
                    float4 v = *(const float4*)(ap + off);
                    sA[off + 0][bb] = v.x; sA[off + 1][bb] = v.y;
                    sA[off + 2][bb] = v.z; sA[off + 3][bb] = v.w;
                }
            }
            {
                int kk = tid >> 3;
                const float* wp = W_in + (size_t)(k0 + kk) * HDIM + n0;
#pragma unroll
                for (int c = 0; c < 4; c++) {
                    int nn = (tid & 7) * 4 + c * 32;
                    *(float4*)&sW[kk][nn] = *(const float4*)(wp + nn);
                }
            }
            __syncthreads();
            mmastep(acc);
            __syncthreads();
        }
#pragma unroll
        for (int j = 0; j < 8; j++) {
            int bb = ty * 8 + j;
#pragma unroll
            for (int p = 0; p < 2; p++) {
                float2 v = unpack2(acc[j][p]);
                int n = n0 + tx * 4 + p * 2;
                *(float2*)&g_part[((size_t)slice * B + bb) * HDIM + n] = v;
            }
        }
    }
    gridbar(nb);

    // ---------- P1: work-stealing pool: 40 FFMA2 GEMM units + 512 attention units ----------
    for (;;) {
        if (tid == 0) s_u = atomicAdd(&g_ctr, 1);
        __syncthreads();
        int u = s_u;
        __syncthreads();
        if (u >= 552) break;

        if (u < 40) {
            bool isGates = (u < 32);
            int n0 = isGates ? u * 128 : (u - 32) * 128;
            ull acc[8][2];
#pragma unroll
            for (int j = 0; j < 8; j++) { acc[j][0] = 0ULL; acc[j][1] = 0ULL; }

            {
                const float* Wp = isGates ? W_hh : (W_out + 1024);
                int ldw = isGates ? 1024 : 2048;
                for (int k0 = 0; k0 < 1024; k0 += 32) {
                    {
                        int bb = tid >> 2, kq = (tid & 3) * 4;
                        const float* ap = h0 + (size_t)bb * 1024 + k0;
#pragma unroll
                        for (int c = 0; c < 2; c++) {
                            int off = kq + c * 16;
                            float4 v = *(const float4*)(ap + off);
                            sA[off + 0][bb] = v.x; sA[off + 1][bb] = v.y;
                            sA[off + 2][bb] = v.z; sA[off + 3][bb] = v.w;
                        }
                    }
                    {
                        int n = tid >> 1, half = (tid & 1) * 16;
                        const float* wp = Wp + (size_t)(n0 + n) * ldw + k0 + half;
#pragma unroll
                        for (int c = 0; c < 4; c++) {
                            int off = half + c * 4;
                            float4 v = *(const float4*)(wp + c * 4);
                            sW[off + 0][n] = v.x; sW[off + 1][n] = v.y;
                            sW[off + 2][n] = v.z; sW[off + 3][n] = v.w;
                        }
                    }
                    __syncthreads();
                    mmastep(acc);
                    __syncthreads();
                }
            }
            if (isGates) {
                for (int k0 = 0; k0 < EDIM; k0 += 32) {
                    {
                        int bb = tid >> 2, kq = (tid & 3) * 4;
                        int tok = tokens[bb];
                        const float* ap = emb + (size_t)tok * EDIM + k0;
#pragma unroll
                        for (int c = 0; c < 2; c++) {
                            int off = kq + c * 16;
#pragma unroll
                            for (int i = 0; i < 4; i++)
                                sA[off + i][bb] = (k0 + off + i < EDIM) ? ap[off + i] : 0.f;
                        }
                    }
                    {
                        int n = tid >> 1, half = (tid & 1) * 16;
                        const float* wp = W_ih + (size_t)(n0 + n) * KCAT + 1024 + k0 + half;
#pragma unroll
                        for (int c = 0; c < 4; c++) {
                            int off = half + c * 4;
#pragma unroll
                            for (int i = 0; i < 4; i++)
                                sW[off + i][n] = (k0 + off + i < EDIM) ? wp[c * 4 + i] : 0.f;
                        }
                    }
                    __syncthreads();
                    mmastep(acc);
                    __syncthreads();
                }
            }
#pragma unroll
            for (int j = 0; j < 8; j++) {
                int bb = ty * 8 + j;
#pragma unroll
                for (int p = 0; p < 2; p++) {
                    float2 v = unpack2(acc[j][p]);
                    int n = n0 + tx * 4 + p * 2;
                    if (isGates) {
                        v.x += b_ih[n] + b_hh[n];
                        v.y += b_ih[n + 1] + b_hh[n + 1];
                        *(float2*)&g_pgates[bb * G4 + n] = v;
                    } else {
                        *(float2*)&g_pctx[bb * HDIM + n] = v;
                    }
                }
            }
        } else {
            // attention unit
            int au = u - 40;
            int b = au & 63, sg = au >> 6;
            int warp = tid >> 5, lane = tid & 31;
            int wg = sg * 8 + warp;

            {   // q = sum of 8 split-K partials
                const float4* qp = (const float4*)g_part;
                float4 a = make_float4(0.f, 0.f, 0.f, 0.f);
#pragma unroll
                for (int s = 0; s < 8; s++) {
                    float4 t = qp[((size_t)s * B + b) * 256 + tid];
                    a.x += t.x; a.y += t.y; a.z += t.z; a.w += t.w;
                }
                sq[tid] = a;
            }
            __syncthreads();

            float4 av[8];
#pragma unroll
            for (int j = 0; j < 8; j++) av[j] = make_float4(0.f, 0.f, 0.f, 0.f);
            float m = -1e30f, l = 0.f;

            int s0r = wg * 32;
            for (int r = 0; r < 32; r++) {
                const float4* row = (const float4*)(enc + ((size_t)(s0r + r) * B + b) * HDIM);
                float4 e[8];
#pragma unroll
                for (int j = 0; j < 8; j++) e[j] = row[j * 32 + lane];
                float d = 0.f;
#pragma unroll
                for (int j = 0; j < 8; j++) {
                    float4 q = sq[j * 32 + lane];
                    d += e[j].x * q.x + e[j].y * q.y + e[j].z * q.z + e[j].w * q.w;
                }
#pragma unroll
                for (int off = 16; off > 0; off >>= 1)
                    d += __shfl_xor_sync(0xffffffffu, d, off);

                float mn  = fmaxf(m, d);
                float fac = __expf(m - mn);
                float p   = __expf(d - mn);
                l = l * fac + p;
                m = mn;
#pragma unroll
                for (int j = 0; j < 8; j++) {
                    av[j].x = av[j].x * fac + p * e[j].x;
                    av[j].y = av[j].y * fac + p * e[j].y;
                    av[j].z = av[j].z * fac + p * e[j].z;
                    av[j].w = av[j].w * fac + p * e[j].w;
                }
            }
            int pi = b * 64 + wg;
            if (lane == 0) { g_pm[pi] = m; g_pl[pi] = l; }
            float4* pa = (float4*)(g_pacc + (size_t)pi * HDIM);
#pragma unroll
            for (int j = 0; j < 8; j++) pa[j * 32 + lane] = av[j];
        }
        __syncthreads();
    }
    gridbar(nb);
    if (cta == 0 && tid == 0) g_ctr = 0;  // reset steal counter for next replay

    // ---------- P2: context combine ----------
    if (cta < 64) {
        int b = cta, t = tid;
        float M = -1e30f;
        for (int c = 0; c < 64; c++) M = fmaxf(M, g_pm[b * 64 + c]);
        float lsum = 0.f;
        float4 ctx = make_float4(0.f, 0.f, 0.f, 0.f);
        for (int c = 0; c < 64; c++) {
            float fac = __expf(g_pm[b * 64 + c] - M);
            lsum += fac * g_pl[b * 64 + c];
            float4 a = *(const float4*)(g_pacc + (size_t)(b * 64 + c) * HDIM + t * 4);
            ctx.x += fac * a.x; ctx.y += fac * a.y;
            ctx.z += fac * a.z; ctx.w += fac * a.w;
        }
        float inv = 1.f / lsum;
        *(float4*)&g_ctxc[b * HDIM + t * 4] =
            make_float4(ctx.x * inv, ctx.y * inv, ctx.z * inv, ctx.w * inv);
    }
    gridbar(nb);

    // ---------- P3: ctx GEMM (16 tiles x 8 k-slices) ----------
    if (cta < 128) {
        int tile = cta >> 3, slice = cta & 7;
        gemm_unit<false>(g_ctxc, HDIM, W_out, 2 * HDIM,
                         tile * 64, slice * 2, slice * 2 + 2, HDIM,
                         g_part + CTX_OFF + (size_t)slice * B * HDIM, 0, nullptr, sm);
    }
    gridbar(nb);

    // ---------- P4: combine + tanh -> ctx_hat ----------
    for (int i = cta * 256 + tid; i < B * HDIM; i += nb * 256) {
        int b = i >> 10, n = i & 1023;
        float v = g_pctx[i];
#pragma unroll
        for (int s = 0; s < 8; s++) v += g_part[CTX_OFF + ((size_t)s * B + b) * HDIM + n];
        g_ctxh[i] = tanhf(v);
    }
    gridbar(nb);

    // ---------- P5: gates GEMM (64 tiles x 2 k-slices) ----------
    if (cta < 128) {
        int tile = cta >> 1, slice = cta & 1;
        gemm_unit<false>(g_ctxh, HDIM, W_ih, KCAT,
                         tile * 64, slice * 8, slice * 8 + 8, G4,
                         g_part + GATES_OFF + (size_t)slice * B * G4, 0, nullptr, sm);
    }
    gridbar(nb);

    // ---------- P6: gates combine + LSTM ----------
    for (int i = cta * 256 + tid; i < B * HDIM; i += nb * 256) {
        int b = i >> 10, h = i & 1023;
        const float* pg = g_pgates + (size_t)b * G4;
        float gi = pg[h], gf = pg[HDIM + h], gg = pg[2 * HDIM + h], go = pg[3 * HDIM + h];
#pragma unroll
        for (int s = 0; s < 2; s++) {
            const float* p = g_part + GATES_OFF + ((size_t)s * B + b) * (size_t)G4;
            gi += p[h]; gf += p[HDIM + h]; gg += p[2 * HDIM + h]; go += p[3 * HDIM + h];
        }
        float si = 1.f / (1.f + __expf(-gi));
        float sf = 1.f / (1.f + __expf(-gf));
        float so = 1.f / (1.f + __expf(-go));
        float cn = sf * c0[i] + si * tanhf(gg);
        float hn = so * tanhf(cn);
        g_hN[i] = hn;
        out[(size_t)B * VDIM + i] = hn;
        out[(size_t)B * VDIM + (size_t)B * HDIM + i] = cn;
    }
    gridbar(nb);

    // ---------- P7: logits (364 tiles strided over grid) ----------
    for (int u = cta; u < (VDIM + 63) / 64; u += nb) {
        gemm_unit<true>(g_hN, HDIM, W_gen, HDIM,
                        u * 64, 0, 16, VDIM,
                        out, VDIM, b_gen, sm);
        __syncthreads();
    }
}

// ---------------- host launch ----------------
extern "C" void kernel_launch(void* const* d_in, const int* in_sizes, int n_in,
                              void* d_out, int out_size)
{
    const int*   tokens = (const int*)  d_in[0];
    const float* enc    = (const float*)d_in[1];
    const float* h0     = (const float*)d_in[2];
    const float* c0     = (const float*)d_in[3];
    const float* emb    = (const float*)d_in[4];
    const float* W_in   = (const float*)d_in[5];
    const float* W_out  = (const float*)d_in[6];
    const float* W_ih   = (const float*)d_in[7];
    const float* W_hh   = (const float*)d_in[8];
    const float* b_ih   = (const float*)d_in[9];
    const float* b_hh   = (const float*)d_in[10];
    const float* W_gen  = (const float*)d_in[11];
    const float* b_gen  = (const float*)d_in[12];
    float* out = (float*)d_out;

    const int SMH = 98304;
    cudaFuncSetAttribute(k_uber, cudaFuncAttributeMaxDynamicSharedMemorySize, SMH);

    k_uber<<<296, 256, SMH>>>(enc, tokens, emb, h0, c0,
                              W_in, W_out, W_ih, W_hh, b_ih, b_hh,
                              W_gen, b_gen, out);
}

// round 12
// speedup vs baseline: 1.2681x; 1.2681x over previous
#include <cuda_runtime.h>
#include <cuda_bf16.h>
#include <cstdint>

#define B    64
#define HDIM 1024
#define VDIM 23262
#define EDIM 300
#define G4   4096
#define KCAT (HDIM + EDIM)

#define CTX_OFF   1048576
#define GATES_OFF 2097152

typedef unsigned long long ull;

// ---------------- scratch ----------------
__device__ float g_pm[B * 32];
__device__ float g_pl[B * 32];
__device__ float g_pacc[(size_t)B * 32 * HDIM];
__device__ float g_ctxc[B * HDIM];
__device__ float g_ctxh[B * HDIM];
__device__ float g_pctx[B * HDIM];
__device__ float g_pgates[B * G4];
__device__ float g_hN[B * HDIM];
__device__ float g_part[(size_t)4 * 1024 * 1024];
__device__ int g_bar_cnt;
__device__ volatile int g_bar_gen;

// ---------------- fp32x2 helpers ----------------
__device__ __forceinline__ void ffma2(ull& d, ull a, ull w) {
    asm("fma.rn.f32x2 %0, %1, %2, %0;" : "+l"(d) : "l"(a), "l"(w));
}
__device__ __forceinline__ ull pack_dup(float x) {
    ull r; asm("mov.b64 %0, {%1, %1};" : "=l"(r) : "f"(x)); return r;
}
__device__ __forceinline__ float2 unpack2(ull v) {
    float2 r; asm("mov.b64 {%0, %1}, %2;" : "=f"(r.x), "=f"(r.y) : "l"(v)); return r;
}

// ---------------- HMMA helpers ----------------
__device__ __forceinline__ uint32_t swzf(uint32_t o) { return o ^ ((o >> 3) & 0x70); }

__device__ __forceinline__ void cvt16(const float* v, uint32_t* h, uint32_t* l) {
#pragma unroll
    for (int j = 0; j < 8; j++) {
        uint32_t u0 = __float_as_uint(v[2 * j]);
        uint32_t u1 = __float_as_uint(v[2 * j + 1]);
        asm("prmt.b32 %0, %1, %2, 0x7632;" : "=r"(h[j]) : "r"(u0), "r"(u1));
        float l0 = v[2 * j]     - __uint_as_float(u0 & 0xFFFF0000u);
        float l1 = v[2 * j + 1] - __uint_as_float(u1 & 0xFFFF0000u);
        asm("cvt.rn.bf16x2.f32 %0, %1, %2;" : "=r"(l[j]) : "f"(l1), "f"(l0));
    }
}
__device__ __forceinline__ void ldsm4(uint32_t& r0, uint32_t& r1, uint32_t& r2, uint32_t& r3,
                                      uint32_t addr) {
    asm volatile("ldmatrix.sync.aligned.m8n8.x4.shared.b16 {%0,%1,%2,%3}, [%4];"
                 : "=r"(r0), "=r"(r1), "=r"(r2), "=r"(r3) : "r"(addr));
}
__device__ __forceinline__ void hmma(float* c, const uint32_t* a, const uint32_t* b) {
    asm volatile("mma.sync.aligned.m16n8k16.row.col.f32.bf16.bf16.f32 "
                 "{%0,%1,%2,%3}, {%4,%5,%6,%7}, {%8,%9}, {%0,%1,%2,%3};"
                 : "+f"(c[0]), "+f"(c[1]), "+f"(c[2]), "+f"(c[3])
                 : "r"(a[0]), "r"(a[1]), "r"(a[2]), "r"(a[3]), "r"(b[0]), "r"(b[1]));
}
__device__ __forceinline__ void cpasync16(uint32_t dst, const void* src, int szbytes) {
    asm volatile("cp.async.cg.shared.global [%0], [%1], 16, %2;"
                 :: "r"(dst), "l"(src), "r"(szbytes) : "memory");
}

// ---------------- grid-wide barrier (persistent, replay-safe) ----------------
__device__ __forceinline__ void gridbar(int nb) {
    __syncthreads();
    if (threadIdx.x == 0) {
        __threadfence();
        int gen = g_bar_gen;
        if (atomicAdd(&g_bar_cnt, 1) == nb - 1) {
            g_bar_cnt = 0;
            __threadfence();
            g_bar_gen = gen + 1;
        } else {
            while (g_bar_gen == gen) __nanosleep(128);
            __threadfence();
        }
    }
    __syncthreads();
}

// ================= hmma bf16-split GEMM unit (device fn) =================
template <bool DIRECT>
__device__ __forceinline__ void gemm_unit(
    const float* __restrict__ A, int K,
    const float* __restrict__ W, int ldw,
    int n0, int cs, int ce, int N,
    float* __restrict__ dst, int ldc, const float* __restrict__ bias,
    char* sm)
{
    int tid = threadIdx.x, wid = tid >> 5, lane = tid & 31;
    int g = lane >> 2, tig = lane & 3;
    int mbase = (wid >> 1) * 16, nbase = (wid & 1) * 32;
    uint32_t smb = (uint32_t)__cvta_generic_to_shared(sm);
    int frow = tid >> 2, fqd = tid & 3;

    int la = lane & 7, lb3 = (lane >> 3) & 1, lb4 = (lane >> 4) & 1;
    uint32_t rawA  = (uint32_t)(mbase + la + lb3 * 8) * 128 + (uint32_t)lb4 * 16;
    uint32_t xorA  = (rawA >> 3) & 0x70;
    uint32_t rawB0 = (uint32_t)(nbase + la + lb4 * 8) * 128 + (uint32_t)lb3 * 16;
    uint32_t rawB1 = rawB0 + 2048;
    uint32_t xorB0 = (rawB0 >> 3) & 0x70;
    uint32_t xorB1 = (rawB1 >> 3) & 0x70;
    uint32_t so0 = swzf((uint32_t)frow * 128 + (uint32_t)fqd * 32);
    uint32_t so1 = so0 ^ 16;

    float acc[4][4];
#pragma unroll
    for (int nf = 0; nf < 4; nf++)
#pragma unroll
        for (int j = 0; j < 4; j++) acc[nf][j] = 0.f;

    auto issue = [&](int kc, int buf) {
        int k0 = kc * 64 + fqd * 16;
        uint32_t da = smb + (uint32_t)buf * 32768 + (uint32_t)frow * 256 + (uint32_t)fqd * 64;
        const float* pA = A + (size_t)frow * K + k0;
#pragma unroll
        for (int q = 0; q < 4; q++) cpasync16(da + q * 16, pA + q * 4, 16);
        bool rv = (n0 + frow) < N;
        const float* pW = W + (size_t)(rv ? (n0 + frow) : 0) * ldw + k0;
        uint32_t dw = da + 16384;
#pragma unroll
        for (int q = 0; q < 4; q++) cpasync16(dw + q * 16, pW + q * 4, rv ? 16 : 0);
        asm volatile("cp.async.commit_group;" ::: "memory");
    };

    auto convertbuf = [&](int buf) {
        char* rb = sm + buf * 32768;
        float v[16];
        uint32_t h[8], l[8];
#pragma unroll
        for (int half = 0; half < 2; half++) {
            const float4* r4 = (const float4*)(rb + half * 16384 + frow * 256 + fqd * 64);
            float4 a = r4[0], b4 = r4[1], c4 = r4[2], d4 = r4[3];
            v[0]=a.x; v[1]=a.y; v[2]=a.z; v[3]=a.w;
            v[4]=b4.x; v[5]=b4.y; v[6]=b4.z; v[7]=b4.w;
            v[8]=c4.x; v[9]=c4.y; v[10]=c4.z; v[11]=c4.w;
            v[12]=d4.x; v[13]=d4.y; v[14]=d4.z; v[15]=d4.w;
            cvt16(v, h, l);
            char* d = sm + 65536 + half * 16384;
            *(uint4*)(d + so0)        = make_uint4(h[0], h[1], h[2], h[3]);
            *(uint4*)(d + so1)        = make_uint4(h[4], h[5], h[6], h[7]);
            *(uint4*)(d + 8192 + so0) = make_uint4(l[0], l[1], l[2], l[3]);
            *(uint4*)(d + 8192 + so1) = make_uint4(l[4], l[5], l[6], l[7]);
        }
    };

    if (cs < ce) issue(cs, 0);
    uint32_t bfA = smb + 65536, bfW = smb + 81920;

    for (int ci = cs; ci < ce; ci++) {
        int buf = (ci - cs) & 1;
        asm volatile("cp.async.wait_group 0;" ::: "memory");
        __syncthreads();
        convertbuf(buf);
        if (ci + 1 < ce) issue(ci + 1, buf ^ 1);
        __syncthreads();

#pragma unroll
        for (int ks = 0; ks < 4; ks++) {
            uint32_t kb = (uint32_t)ks * 32;
            uint32_t aA = bfA + ((rawA + kb) ^ xorA);
            uint32_t ah[4], al[4];
            ldsm4(ah[0], ah[1], ah[2], ah[3], aA);
            ldsm4(al[0], al[1], al[2], al[3], aA + 8192);
            uint32_t b0 = bfW + ((rawB0 + kb) ^ xorB0);
            uint32_t b1 = bfW + ((rawB1 + kb) ^ xorB1);
            uint32_t bh[8], bl[8];
            ldsm4(bh[0], bh[1], bh[2], bh[3], b0);
            ldsm4(bh[4], bh[5], bh[6], bh[7], b1);
            ldsm4(bl[0], bl[1], bl[2], bl[3], b0 + 8192);
            ldsm4(bl[4], bl[5], bl[6], bl[7], b1 + 8192);
#pragma unroll
            for (int nf = 0; nf < 4; nf++) {
                hmma(acc[nf], ah, &bh[nf * 2]);
                hmma(acc[nf], ah, &bl[nf * 2]);
                hmma(acc[nf], al, &bh[nf * 2]);
            }
        }
    }

#pragma unroll
    for (int nf = 0; nf < 4; nf++) {
        int row = mbase + g;
        int n   = n0 + nbase + nf * 8 + tig * 2;
        float2 v0 = make_float2(acc[nf][0], acc[nf][1]);
        float2 v1 = make_float2(acc[nf][2], acc[nf][3]);
        if (n < N) {
            if (DIRECT) {
                if (bias) { v0.x += bias[n]; v0.y += bias[n + 1];
                            v1.x += bias[n]; v1.y += bias[n + 1]; }
                *(float2*)&dst[(size_t)row * ldc + n]       = v0;
                *(float2*)&dst[(size_t)(row + 8) * ldc + n] = v1;
            } else {
                *(float2*)&dst[(size_t)row * N + n]       = v0;
                *(float2*)&dst[(size_t)(row + 8) * N + n] = v1;
            }
        }
    }
}

// ---------------- fp32 skinny GEMM (q projection; W [K,N] n-major; split-K partials) ----------------
__global__ __launch_bounds__(256) void k_gemm_nk(
    const float* __restrict__ A, int lda,
    const float* __restrict__ W, int ldw,
    float* __restrict__ C, int N, int K, int nsl)
{
    __shared__ float sW[32][128];
    __shared__ float sA[32][64];
    int tid = threadIdx.x;
    int tx = tid & 31, ty = tid >> 5;
    int n0 = blockIdx.x * 128;

    int nk32 = K >> 5;
    int per  = (nk32 + nsl - 1) / nsl;
    int k0s  = blockIdx.y * per * 32;
    int k0e  = min(K, (int)(blockIdx.y + 1) * per * 32);

    ull acc[8][2];
#pragma unroll
    for (int j = 0; j < 8; j++) { acc[j][0] = 0ULL; acc[j][1] = 0ULL; }

    for (int k0 = k0s; k0 < k0e; k0 += 32) {
        {
            int bb = tid >> 2, kq = (tid & 3) * 4;
            const float* ap = A + (size_t)bb * lda + k0;
#pragma unroll
            for (int c = 0; c < 2; c++) {
                int off = kq + c * 16;
                float4 v = *(const float4*)(ap + off);
                sA[off + 0][bb] = v.x; sA[off + 1][bb] = v.y;
                sA[off + 2][bb] = v.z; sA[off + 3][bb] = v.w;
            }
        }
        {
            int kk = tid >> 3;
            const float* wp = W + (size_t)(k0 + kk) * ldw + n0;
#pragma unroll
            for (int c = 0; c < 4; c++) {
                int nn = (tid & 7) * 4 + c * 32;
                *(float4*)&sW[kk][nn] = *(const float4*)(wp + nn);
            }
        }
        __syncthreads();

#pragma unroll 8
        for (int kk = 0; kk < 32; kk++) {
            float4 a0 = *(const float4*)&sA[kk][ty * 8];
            float4 a1 = *(const float4*)&sA[kk][ty * 8 + 4];
            const ull* wp2 = (const ull*)&sW[kk][tx * 4];
            ull w0 = wp2[0], w1 = wp2[1];
            ull ad[8];
            ad[0] = pack_dup(a0.x); ad[1] = pack_dup(a0.y);
            ad[2] = pack_dup(a0.z); ad[3] = pack_dup(a0.w);
            ad[4] = pack_dup(a1.x); ad[5] = pack_dup(a1.y);
            ad[6] = pack_dup(a1.z); ad[7] = pack_dup(a1.w);
#pragma unroll
            for (int j = 0; j < 8; j++) { ffma2(acc[j][0], ad[j], w0); ffma2(acc[j][1], ad[j], w1); }
        }
        __syncthreads();
    }

#pragma unroll
    for (int j = 0; j < 8; j++) {
        int bb = ty * 8 + j;
#pragma unroll
        for (int p = 0; p < 2; p++) {
            float2 v = unpack2(acc[j][p]);
            int n = n0 + tx * 4 + p * 2;
            size_t base = ((size_t)blockIdx.y * B + bb) * (size_t)N;
            *(float2*)&C[base + n] = v;
        }
    }
}

// ================= k_mega: 40 weight-GEMM CTAs + 256 attention CTAs (one wave) =================
__global__ __launch_bounds__(256) void k_mega(
    const float* __restrict__ enc,
    const int* __restrict__ tokens, const float* __restrict__ emb,
    const float* __restrict__ h0,
    const float* __restrict__ W_hh, const float* __restrict__ W_ih,
    const float* __restrict__ W_out,
    const float* __restrict__ b_ih, const float* __restrict__ b_hh)
{
    __shared__ __align__(16) char smu[24576];
    int bid = blockIdx.x;
    int tid = threadIdx.x;

    if (bid < 40) {
        // ---------- FFMA2 weight-GEMM branch ----------
        float (*sW)[128] = (float(*)[128])smu;
        float (*sA)[64]  = (float(*)[64])(smu + 16384);
        int tx = tid & 31, ty = tid >> 5;
        bool isGates = (bid < 32);
        int n0 = isGates ? bid * 128 : (bid - 32) * 128;

        ull acc[8][2];
#pragma unroll
        for (int j = 0; j < 8; j++) { acc[j][0] = 0ULL; acc[j][1] = 0ULL; }

        auto mmastep = [&]() {
#pragma unroll 8
            for (int kk = 0; kk < 32; kk++) {
                float4 a0 = *(const float4*)&sA[kk][ty * 8];
                float4 a1 = *(const float4*)&sA[kk][ty * 8 + 4];
                const ull* wp2 = (const ull*)&sW[kk][tx * 4];
                ull w0 = wp2[0], w1 = wp2[1];
                ull ad[8];
                ad[0] = pack_dup(a0.x); ad[1] = pack_dup(a0.y);
                ad[2] = pack_dup(a0.z); ad[3] = pack_dup(a0.w);
                ad[4] = pack_dup(a1.x); ad[5] = pack_dup(a1.y);
                ad[6] = pack_dup(a1.z); ad[7] = pack_dup(a1.w);
#pragma unroll
                for (int j = 0; j < 8; j++) { ffma2(acc[j][0], ad[j], w0); ffma2(acc[j][1], ad[j], w1); }
            }
        };

        {
            const float* Wp = isGates ? W_hh : (W_out + 1024);
            int ldw = isGates ? 1024 : 2048;
            for (int k0 = 0; k0 < 1024; k0 += 32) {
                {
                    int bb = tid >> 2, kq = (tid & 3) * 4;
                    const float* ap = h0 + (size_t)bb * 1024 + k0;
#pragma unroll
                    for (int c = 0; c < 2; c++) {
                        int off = kq + c * 16;
                        float4 v = *(const float4*)(ap + off);
                        sA[off + 0][bb] = v.x; sA[off + 1][bb] = v.y;
                        sA[off + 2][bb] = v.z; sA[off + 3][bb] = v.w;
                    }
                }
                {
                    int n = tid >> 1, half = (tid & 1) * 16;
                    const float* wp = Wp + (size_t)(n0 + n) * ldw + k0 + half;
#pragma unroll
                    for (int c = 0; c < 4; c++) {
                        int off = half + c * 4;
                        float4 v = *(const float4*)(wp + c * 4);
                        sW[off + 0][n] = v.x; sW[off + 1][n] = v.y;
                        sW[off + 2][n] = v.z; sW[off + 3][n] = v.w;
                    }
                }
                __syncthreads();
                mmastep();
                __syncthreads();
            }
        }
        if (isGates) {
            for (int k0 = 0; k0 < EDIM; k0 += 32) {
                {
                    int bb = tid >> 2, kq = (tid & 3) * 4;
                    int tok = tokens[bb];
                    const float* ap = emb + (size_t)tok * EDIM + k0;
#pragma unroll
                    for (int c = 0; c < 2; c++) {
                        int off = kq + c * 16;
#pragma unroll
                        for (int i = 0; i < 4; i++)
                            sA[off + i][bb] = (k0 + off + i < EDIM) ? ap[off + i] : 0.f;
                    }
                }
                {
                    int n = tid >> 1, half = (tid & 1) * 16;
                    const float* wp = W_ih + (size_t)(n0 + n) * KCAT + 1024 + k0 + half;
#pragma unroll
                    for (int c = 0; c < 4; c++) {
                        int off = half + c * 4;
#pragma unroll
                        for (int i = 0; i < 4; i++)
                            sW[off + i][n] = (k0 + off + i < EDIM) ? wp[c * 4 + i] : 0.f;
                    }
                }
                __syncthreads();
                mmastep();
                __syncthreads();
            }
        }

#pragma unroll
        for (int j = 0; j < 8; j++) {
            int bb = ty * 8 + j;
#pragma unroll
            for (int p = 0; p < 2; p++) {
                float2 v = unpack2(acc[j][p]);
                int n = n0 + tx * 4 + p * 2;
                if (isGates) {
                    v.x += b_ih[n] + b_hh[n];
                    v.y += b_ih[n + 1] + b_hh[n + 1];
                    *(float2*)&g_pgates[bb * G4 + n] = v;
                } else {
                    *(float2*)&g_pctx[bb * HDIM + n] = v;
                }
            }
        }
    } else {
        // ---------- attention branch: 256 CTAs, warp covers 64 s-rows ----------
        float4* sq = (float4*)smu;
        int abid = bid - 40;
        int b = abid & 63, sg = abid >> 6;     // sg in 0..3
        int warp = tid >> 5, lane = tid & 31;
        int wg = sg * 8 + warp;                // 0..31

        {   // q = sum of 4 split-K partials (q launch completed before mega)
            const float4* qp = (const float4*)g_part;
            float4 s0 = qp[(0 * B + b) * 256 + tid];
            float4 s1 = qp[(1 * B + b) * 256 + tid];
            float4 s2 = qp[(2 * B + b) * 256 + tid];
            float4 s3 = qp[(3 * B + b) * 256 + tid];
            sq[tid] = make_float4(s0.x + s1.x + s2.x + s3.x,
                                  s0.y + s1.y + s2.y + s3.y,
                                  s0.z + s1.z + s2.z + s3.z,
                                  s0.w + s1.w + s2.w + s3.w);
        }
        __syncthreads();

        float4 av[8];
#pragma unroll
        for (int j = 0; j < 8; j++) av[j] = make_float4(0.f, 0.f, 0.f, 0.f);
        float m = -1e30f, l = 0.f;

        int s0r = wg * 64;
        for (int r = 0; r < 64; r++) {
            const float4* row = (const float4*)(enc + ((size_t)(s0r + r) * B + b) * HDIM);
            float4 e[8];
#pragma unroll
            for (int j = 0; j < 8; j++) e[j] = row[j * 32 + lane];
            float d = 0.f;
#pragma unroll
            for (int j = 0; j < 8; j++) {
                float4 q = sq[j * 32 + lane];
                d += e[j].x * q.x + e[j].y * q.y + e[j].z * q.z + e[j].w * q.w;
            }
#pragma unroll
            for (int off = 16; off > 0; off >>= 1)
                d += __shfl_xor_sync(0xffffffffu, d, off);

            float mn  = fmaxf(m, d);
            float fac = __expf(m - mn);
            float p   = __expf(d - mn);
            l = l * fac + p;
            m = mn;
#pragma unroll
            for (int j = 0; j < 8; j++) {
                av[j].x = av[j].x * fac + p * e[j].x;
                av[j].y = av[j].y * fac + p * e[j].y;
                av[j].z = av[j].z * fac + p * e[j].z;
                av[j].w = av[j].w * fac + p * e[j].w;
            }
        }
        int pi = b * 32 + wg;
        if (lane == 0) { g_pm[pi] = m; g_pl[pi] = l; }
        float4* pa = (float4*)(g_pacc + (size_t)pi * HDIM);
#pragma unroll
        for (int j = 0; j < 8; j++) pa[j * 32 + lane] = av[j];
    }
}

// ================= k_post: persistent mid-chain =================
__global__ __launch_bounds__(256) void k_post(
    const float* __restrict__ W_out, const float* __restrict__ W_ih,
    const float* __restrict__ c0, float* __restrict__ out)
{
    extern __shared__ char sm[];
    int u = blockIdx.x, tid = threadIdx.x;
    int nb = gridDim.x;

    // P1: context combine (64 CTAs, 32 strips)
    if (u < 64) {
        int b = u, t = tid;
        float M = -1e30f;
        for (int c = 0; c < 32; c++) M = fmaxf(M, g_pm[b * 32 + c]);
        float lsum = 0.f;
        float4 ctx = make_float4(0.f, 0.f, 0.f, 0.f);
        for (int c = 0; c < 32; c++) {
            float fac = __expf(g_pm[b * 32 + c] - M);
            lsum += fac * g_pl[b * 32 + c];
            float4 a = *(const float4*)(g_pacc + (size_t)(b * 32 + c) * HDIM + t * 4);
            ctx.x += fac * a.x; ctx.y += fac * a.y;
            ctx.z += fac * a.z; ctx.w += fac * a.w;
        }
        float inv = 1.f / lsum;
        *(float4*)&g_ctxc[b * HDIM + t * 4] =
            make_float4(ctx.x * inv, ctx.y * inv, ctx.z * inv, ctx.w * inv);
    }
    gridbar(nb);

    // P2: ctx GEMM — 16 n-tiles x 8 k-slices (2 chunks each)
    if (u < 128) {
        int tile = u >> 3, slice = u & 7;
        gemm_unit<false>(g_ctxc, HDIM, W_out, 2 * HDIM,
                         tile * 64, slice * 2, slice * 2 + 2, HDIM,
                         g_part + CTX_OFF + (size_t)slice * B * HDIM, 0, nullptr, sm);
    }
    gridbar(nb);

    // P3: combine 8 slices + pctx, tanh -> ctx_hat
    for (int i = u * 256 + tid; i < B * HDIM; i += nb * 256) {
        int b = i >> 10, n = i & 1023;
        float v = g_pctx[i];
#pragma unroll
        for (int s = 0; s < 8; s++) v += g_part[CTX_OFF + ((size_t)s * B + b) * HDIM + n];
        g_ctxh[i] = tanhf(v);
    }
    gridbar(nb);

    // P4: gates GEMM — 64 n-tiles x 2 k-slices (8 chunks each)
    if (u < 128) {
        int tile = u >> 1, slice = u & 1;
        gemm_unit<false>(g_ctxh, HDIM, W_ih, KCAT,
                         tile * 64, slice * 8, slice * 8 + 8, G4,
                         g_part + GATES_OFF + (size_t)slice * B * G4, 0, nullptr, sm);
    }
    gridbar(nb);

    // P5: gates combine + LSTM
    for (int i = u * 256 + tid; i < B * HDIM; i += nb * 256) {
        int b = i >> 10, h = i & 1023;
        const float* pg = g_pgates + (size_t)b * G4;
        float gi = pg[h], gf = pg[HDIM + h], gg = pg[2 * HDIM + h], go = pg[3 * HDIM + h];
#pragma unroll
        for (int s = 0; s < 2; s++) {
            const float* p = g_part + GATES_OFF + ((size_t)s * B + b) * (size_t)G4;
            gi += p[h]; gf += p[HDIM + h]; gg += p[2 * HDIM + h]; go += p[3 * HDIM + h];
        }
        float si = 1.f / (1.f + __expf(-gi));
        float sf = 1.f / (1.f + __expf(-gf));
        float so = 1.f / (1.f + __expf(-go));
        float cn = sf * c0[i] + si * tanhf(gg);
        float hn = so * tanhf(cn);
        g_hN[i] = hn;
        out[(size_t)B * VDIM + i] = hn;
        out[(size_t)B * VDIM + (size_t)B * HDIM + i] = cn;
    }
}

// ================= k_logits =================
__global__ __launch_bounds__(256, 2) void k_logits(
    const float* __restrict__ W_gen, const float* __restrict__ b_gen,
    float* __restrict__ out)
{
    extern __shared__ char sm[];
    gemm_unit<true>(g_hN, HDIM, W_gen, HDIM,
                    blockIdx.x * 64, 0, 16, VDIM,
                    out, VDIM, b_gen, sm);
}

// ---------------- host launch ----------------
extern "C" void kernel_launch(void* const* d_in, const int* in_sizes, int n_in,
                              void* d_out, int out_size)
{
    const int*   tokens = (const int*)  d_in[0];
    const float* enc    = (const float*)d_in[1];
    const float* h0     = (const float*)d_in[2];
    const float* c0     = (const float*)d_in[3];
    const float* emb    = (const float*)d_in[4];
    const float* W_in   = (const float*)d_in[5];
    const float* W_out  = (const float*)d_in[6];
    const float* W_ih   = (const float*)d_in[7];
    const float* W_hh   = (const float*)d_in[8];
    const float* b_ih   = (const float*)d_in[9];
    const float* b_hh   = (const float*)d_in[10];
    const float* W_gen  = (const float*)d_in[11];
    const float* b_gen  = (const float*)d_in[12];
    float* out = (float*)d_out;

    float* part;
    cudaGetSymbolAddress((void**)&part, g_part);

    const int SMH = 98304;
    cudaFuncSetAttribute(k_post,   cudaFuncAttributeMaxDynamicSharedMemorySize, SMH);
    cudaFuncSetAttribute(k_logits, cudaFuncAttributeMaxDynamicSharedMemorySize, SMH);

    // 1) q partials = h0 @ W_in (split-K 4)
    k_gemm_nk<<<dim3(8, 4), 256>>>(h0, HDIM, W_in, HDIM, part, HDIM, HDIM, 4);

    // 2) mega: one wave = 40 weight-GEMM CTAs + 256 attention CTAs
    k_mega<<<296, 256>>>(enc, tokens, emb, h0, W_hh, W_ih, W_out, b_ih, b_hh);

    // 3) persistent mid-chain
    k_post<<<148, 256, SMH>>>(W_out, W_ih, c0, out);

    // 4) logits = hN @ W_gen^T + b_gen
    k_logits<<<(VDIM + 63) / 64, 256, SMH>>>(W_gen, b_gen, out);
}

// round 13
// speedup vs baseline: 1.4731x; 1.1617x over previous
#include <cuda_runtime.h>
#include <cuda_bf16.h>
#include <cstdint>

#define B    64
#define HDIM 1024
#define VDIM 23262
#define EDIM 300
#define G4   4096
#define KCAT (HDIM + EDIM)

#define CTX_OFF   1048576
#define GATES_OFF 2097152

typedef unsigned long long ull;

// ---------------- scratch ----------------
__device__ float g_pm[B * 64];
__device__ float g_pl[B * 64];
__device__ float g_pacc[(size_t)B * 64 * HDIM];
__device__ float g_ctxc[B * HDIM];
__device__ float g_ctxh[B * HDIM];
__device__ float g_pctx[B * HDIM];
__device__ float g_pgates[B * G4];
__device__ __nv_bfloat16 g_hNh[B * HDIM];
__device__ __nv_bfloat16 g_hNl[B * HDIM];
__device__ float g_part[(size_t)4 * 1024 * 1024];
__device__ int g_qflag;
__device__ int g_bar_cnt;
__device__ volatile int g_bar_gen;

// ---------------- fp32x2 helpers ----------------
__device__ __forceinline__ void ffma2(ull& d, ull a, ull w) {
    asm("fma.rn.f32x2 %0, %1, %2, %0;" : "+l"(d) : "l"(a), "l"(w));
}
__device__ __forceinline__ ull pack_dup(float x) {
    ull r; asm("mov.b64 %0, {%1, %1};" : "=l"(r) : "f"(x)); return r;
}
__device__ __forceinline__ float2 unpack2(ull v) {
    float2 r; asm("mov.b64 {%0, %1}, %2;" : "=f"(r.x), "=f"(r.y) : "l"(v)); return r;
}

// ---------------- HMMA helpers ----------------
__device__ __forceinline__ uint32_t swzf(uint32_t o) { return o ^ ((o >> 3) & 0x70); }

__device__ __forceinline__ void cvt16(const float* v, uint32_t* h, uint32_t* l) {
#pragma unroll
    for (int j = 0; j < 8; j++) {
        uint32_t u0 = __float_as_uint(v[2 * j]);
        uint32_t u1 = __float_as_uint(v[2 * j + 1]);
        asm("prmt.b32 %0, %1, %2, 0x7632;" : "=r"(h[j]) : "r"(u0), "r"(u1));
        float l0 = v[2 * j]     - __uint_as_float(u0 & 0xFFFF0000u);
        float l1 = v[2 * j + 1] - __uint_as_float(u1 & 0xFFFF0000u);
        asm("cvt.rn.bf16x2.f32 %0, %1, %2;" : "=r"(l[j]) : "f"(l1), "f"(l0));
    }
}
__device__ __forceinline__ void ldsm4(uint32_t& r0, uint32_t& r1, uint32_t& r2, uint32_t& r3,
                                      uint32_t addr) {
    asm volatile("ldmatrix.sync.aligned.m8n8.x4.shared.b16 {%0,%1,%2,%3}, [%4];"
                 : "=r"(r0), "=r"(r1), "=r"(r2), "=r"(r3) : "r"(addr));
}
__device__ __forceinline__ void hmma(float* c, const uint32_t* a, const uint32_t* b) {
    asm volatile("mma.sync.aligned.m16n8k16.row.col.f32.bf16.bf16.f32 "
                 "{%0,%1,%2,%3}, {%4,%5,%6,%7}, {%8,%9}, {%0,%1,%2,%3};"
                 : "+f"(c[0]), "+f"(c[1]), "+f"(c[2]), "+f"(c[3])
                 : "r"(a[0]), "r"(a[1]), "r"(a[2]), "r"(a[3]), "r"(b[0]), "r"(b[1]));
}
__device__ __forceinline__ void cpasync16(uint32_t dst, const void* src, int szbytes) {
    asm volatile("cp.async.cg.shared.global [%0], [%1], 16, %2;"
                 :: "r"(dst), "l"(src), "r"(szbytes) : "memory");
}

// ---------------- grid-wide barrier ----------------
__device__ __forceinline__ void gridbar(int nb) {
    __syncthreads();
    if (threadIdx.x == 0) {
        __threadfence();
        int gen = g_bar_gen;
        if (atomicAdd(&g_bar_cnt, 1) == nb - 1) {
            g_bar_cnt = 0;
            __threadfence();
            g_bar_gen = gen + 1;
        } else {
            while (g_bar_gen == gen) __nanosleep(128);
            __threadfence();
        }
    }
    __syncthreads();
}

// ================= hmma bf16-split GEMM unit (post phases) =================
template <bool DIRECT>
__device__ __forceinline__ void gemm_unit(
    const float* __restrict__ A, int K,
    const float* __restrict__ W, int ldw,
    int n0, int cs, int ce, int N,
    float* __restrict__ dst, int ldc, const float* __restrict__ bias,
    char* sm)
{
    int tid = threadIdx.x, wid = tid >> 5, lane = tid & 31;
    int g = lane >> 2, tig = lane & 3;
    int mbase = (wid >> 1) * 16, nbase = (wid & 1) * 32;
    uint32_t smb = (uint32_t)__cvta_generic_to_shared(sm);
    int frow = tid >> 2, fqd = tid & 3;

    int la = lane & 7, lb3 = (lane >> 3) & 1, lb4 = (lane >> 4) & 1;
    uint32_t rawA  = (uint32_t)(mbase + la + lb3 * 8) * 128 + (uint32_t)lb4 * 16;
    uint32_t xorA  = (rawA >> 3) & 0x70;
    uint32_t rawB0 = (uint32_t)(nbase + la + lb4 * 8) * 128 + (uint32_t)lb3 * 16;
    uint32_t rawB1 = rawB0 + 2048;
    uint32_t xorB0 = (rawB0 >> 3) & 0x70;
    uint32_t xorB1 = (rawB1 >> 3) & 0x70;
    uint32_t so0 = swzf((uint32_t)frow * 128 + (uint32_t)fqd * 32);
    uint32_t so1 = so0 ^ 16;

    float acc[4][4];
#pragma unroll
    for (int nf = 0; nf < 4; nf++)
#pragma unroll
        for (int j = 0; j < 4; j++) acc[nf][j] = 0.f;

    auto issue = [&](int kc, int buf) {
        int k0 = kc * 64 + fqd * 16;
        uint32_t da = smb + (uint32_t)buf * 32768 + (uint32_t)frow * 256 + (uint32_t)fqd * 64;
        const float* pA = A + (size_t)frow * K + k0;
#pragma unroll
        for (int q = 0; q < 4; q++) cpasync16(da + q * 16, pA + q * 4, 16);
        bool rv = (n0 + frow) < N;
        const float* pW = W + (size_t)(rv ? (n0 + frow) : 0) * ldw + k0;
        uint32_t dw = da + 16384;
#pragma unroll
        for (int q = 0; q < 4; q++) cpasync16(dw + q * 16, pW + q * 4, rv ? 16 : 0);
        asm volatile("cp.async.commit_group;" ::: "memory");
    };

    auto convertbuf = [&](int buf) {
        char* rb = sm + buf * 32768;
        float v[16];
        uint32_t h[8], l[8];
#pragma unroll
        for (int half = 0; half < 2; half++) {
            const float4* r4 = (const float4*)(rb + half * 16384 + frow * 256 + fqd * 64);
            float4 a = r4[0], b4 = r4[1], c4 = r4[2], d4 = r4[3];
            v[0]=a.x; v[1]=a.y; v[2]=a.z; v[3]=a.w;
            v[4]=b4.x; v[5]=b4.y; v[6]=b4.z; v[7]=b4.w;
            v[8]=c4.x; v[9]=c4.y; v[10]=c4.z; v[11]=c4.w;
            v[12]=d4.x; v[13]=d4.y; v[14]=d4.z; v[15]=d4.w;
            cvt16(v, h, l);
            char* d = sm + 65536 + half * 16384;
            *(uint4*)(d + so0)        = make_uint4(h[0], h[1], h[2], h[3]);
            *(uint4*)(d + so1)        = make_uint4(h[4], h[5], h[6], h[7]);
            *(uint4*)(d + 8192 + so0) = make_uint4(l[0], l[1], l[2], l[3]);
            *(uint4*)(d + 8192 + so1) = make_uint4(l[4], l[5], l[6], l[7]);
        }
    };

    if (cs < ce) issue(cs, 0);
    uint32_t bfA = smb + 65536, bfW = smb + 81920;

    for (int ci = cs; ci < ce; ci++) {
        int buf = (ci - cs) & 1;
        asm volatile("cp.async.wait_group 0;" ::: "memory");
        __syncthreads();
        convertbuf(buf);
        if (ci + 1 < ce) issue(ci + 1, buf ^ 1);
        __syncthreads();

#pragma unroll
        for (int ks = 0; ks < 4; ks++) {
            uint32_t kb = (uint32_t)ks * 32;
            uint32_t aA = bfA + ((rawA + kb) ^ xorA);
            uint32_t ah[4], al[4];
            ldsm4(ah[0], ah[1], ah[2], ah[3], aA);
            ldsm4(al[0], al[1], al[2], al[3], aA + 8192);
            uint32_t b0 = bfW + ((rawB0 + kb) ^ xorB0);
            uint32_t b1 = bfW + ((rawB1 + kb) ^ xorB1);
            uint32_t bh[8], bl[8];
            ldsm4(bh[0], bh[1], bh[2], bh[3], b0);
            ldsm4(bh[4], bh[5], bh[6], bh[7], b1);
            ldsm4(bl[0], bl[1], bl[2], bl[3], b0 + 8192);
            ldsm4(bl[4], bl[5], bl[6], bl[7], b1 + 8192);
#pragma unroll
            for (int nf = 0; nf < 4; nf++) {
                hmma(acc[nf], ah, &bh[nf * 2]);
                hmma(acc[nf], ah, &bl[nf * 2]);
                hmma(acc[nf], al, &bh[nf * 2]);
            }
        }
    }

#pragma unroll
    for (int nf = 0; nf < 4; nf++) {
        int row = mbase + g;
        int n   = n0 + nbase + nf * 8 + tig * 2;
        float2 v0 = make_float2(acc[nf][0], acc[nf][1]);
        float2 v1 = make_float2(acc[nf][2], acc[nf][3]);
        if (n < N) {
            if (DIRECT) {
                if (bias) { v0.x += bias[n]; v0.y += bias[n + 1];
                            v1.x += bias[n]; v1.y += bias[n + 1]; }
                *(float2*)&dst[(size_t)row * ldc + n]       = v0;
                *(float2*)&dst[(size_t)(row + 8) * ldc + n] = v1;
            } else {
                *(float2*)&dst[(size_t)row * N + n]       = v0;
                *(float2*)&dst[(size_t)(row + 8) * N + n] = v1;
            }
        }
    }
}

// ================= k_mega (R9 config): q + indep GEMMs + attention =================
__global__ __launch_bounds__(256) void k_mega(
    const float* __restrict__ enc,
    const int* __restrict__ tokens, const float* __restrict__ emb,
    const float* __restrict__ h0,
    const float* __restrict__ W_hh, const float* __restrict__ W_ih,
    const float* __restrict__ W_out, const float* __restrict__ W_in,
    const float* __restrict__ b_ih, const float* __restrict__ b_hh)
{
    __shared__ __align__(16) char smu[24576];
    int bid = blockIdx.x;
    int tid = threadIdx.x;

    if (bid < 72) {
        float (*sW)[128] = (float(*)[128])smu;
        float (*sA)[64]  = (float(*)[64])(smu + 16384);
        int tx = tid & 31, ty = tid >> 5;

        ull acc[8][2];
#pragma unroll
        for (int j = 0; j < 8; j++) { acc[j][0] = 0ULL; acc[j][1] = 0ULL; }

        auto mmastep = [&]() {
#pragma unroll 8
            for (int kk = 0; kk < 32; kk++) {
                float4 a0 = *(const float4*)&sA[kk][ty * 8];
                float4 a1 = *(const float4*)&sA[kk][ty * 8 + 4];
                const ull* wp2 = (const ull*)&sW[kk][tx * 4];
                ull w0 = wp2[0], w1 = wp2[1];
                ull ad[8];
                ad[0] = pack_dup(a0.x); ad[1] = pack_dup(a0.y);
                ad[2] = pack_dup(a0.z); ad[3] = pack_dup(a0.w);
                ad[4] = pack_dup(a1.x); ad[5] = pack_dup(a1.y);
                ad[6] = pack_dup(a1.z); ad[7] = pack_dup(a1.w);
#pragma unroll
                for (int j = 0; j < 8; j++) { ffma2(acc[j][0], ad[j], w0); ffma2(acc[j][1], ad[j], w1); }
            }
        };

        if (bid < 32) {
            int n0 = (bid & 7) * 128;
            int slice = bid >> 3;
            int k0s = slice * 256, k0e = k0s + 256;
            for (int k0 = k0s; k0 < k0e; k0 += 32) {
                {
                    int bb = tid >> 2, kq = (tid & 3) * 4;
                    const float* ap = h0 + (size_t)bb * HDIM + k0;
#pragma unroll
                    for (int c = 0; c < 2; c++) {
                        int off = kq + c * 16;
                        float4 v = *(const float4*)(ap + off);
                        sA[off + 0][bb] = v.x; sA[off + 1][bb] = v.y;
                        sA[off + 2][bb] = v.z; sA[off + 3][bb] = v.w;
                    }
                }
                {
                    int kk = tid >> 3;
                    const float* wp = W_in + (size_t)(k0 + kk) * HDIM + n0;
#pragma unroll
                    for (int c = 0; c < 4; c++) {
                        int nn = (tid & 7) * 4 + c * 32;
                        *(float4*)&sW[kk][nn] = *(const float4*)(wp + nn);
                    }
                }
                __syncthreads();
                mmastep();
                __syncthreads();
            }
#pragma unroll
            for (int j = 0; j < 8; j++) {
                int bb = ty * 8 + j;
#pragma unroll
                for (int p = 0; p < 2; p++) {
                    float2 v = unpack2(acc[j][p]);
                    int n = n0 + tx * 4 + p * 2;
                    *(float2*)&g_part[((size_t)slice * B + bb) * HDIM + n] = v;
                }
            }
            __threadfence();
            __syncthreads();
            if (tid == 0) atomicAdd(&g_qflag, 1);
            return;
        }

        bool isGates = (bid < 64);
        int n0 = isGates ? (bid - 32) * 128 : (bid - 64) * 128;

        {
            const float* Wp = isGates ? W_hh : (W_out + 1024);
            int ldw = isGates ? 1024 : 2048;
            for (int k0 = 0; k0 < 1024; k0 += 32) {
                {
                    int bb = tid >> 2, kq = (tid & 3) * 4;
                    const float* ap = h0 + (size_t)bb * 1024 + k0;
#pragma unroll
                    for (int c = 0; c < 2; c++) {
                        int off = kq + c * 16;
                        float4 v = *(const float4*)(ap + off);
                        sA[off + 0][bb] = v.x; sA[off + 1][bb] = v.y;
                        sA[off + 2][bb] = v.z; sA[off + 3][bb] = v.w;
                    }
                }
                {
                    int n = tid >> 1, half = (tid & 1) * 16;
                    const float* wp = Wp + (size_t)(n0 + n) * ldw + k0 + half;
#pragma unroll
                    for (int c = 0; c < 4; c++) {
                        int off = half + c * 4;
                        float4 v = *(const float4*)(wp + c * 4);
                        sW[off + 0][n] = v.x; sW[off + 1][n] = v.y;
                        sW[off + 2][n] = v.z; sW[off + 3][n] = v.w;
                    }
                }
                __syncthreads();
                mmastep();
                __syncthreads();
            }
        }
        if (isGates) {
            for (int k0 = 0; k0 < EDIM; k0 += 32) {
                {
                    int bb = tid >> 2, kq = (tid & 3) * 4;
                    int tok = tokens[bb];
                    const float* ap = emb + (size_t)tok * EDIM + k0;
#pragma unroll
                    for (int c = 0; c < 2; c++) {
                        int off = kq + c * 16;
#pragma unroll
                        for (int i = 0; i < 4; i++)
                            sA[off + i][bb] = (k0 + off + i < EDIM) ? ap[off + i] : 0.f;
                    }
                }
                {
                    int n = tid >> 1, half = (tid & 1) * 16;
                    const float* wp = W_ih + (size_t)(n0 + n) * KCAT + 1024 + k0 + half;
#pragma unroll
                    for (int c = 0; c < 4; c++) {
                        int off = half + c * 4;
#pragma unroll
                        for (int i = 0; i < 4; i++)
                            sW[off + i][n] = (k0 + off + i < EDIM) ? wp[c * 4 + i] : 0.f;
                    }
                }
                __syncthreads();
                mmastep();
                __syncthreads();
            }
        }

#pragma unroll
        for (int j = 0; j < 8; j++) {
            int bb = ty * 8 + j;
#pragma unroll
            for (int p = 0; p < 2; p++) {
                float2 v = unpack2(acc[j][p]);
                int n = n0 + tx * 4 + p * 2;
                if (isGates) {
                    v.x += b_ih[n] + b_hh[n];
                    v.y += b_ih[n + 1] + b_hh[n + 1];
                    *(float2*)&g_pgates[bb * G4 + n] = v;
                } else {
                    *(float2*)&g_pctx[bb * HDIM + n] = v;
                }
            }
        }
    } else {
        float4* sq = (float4*)smu;
        int abid = bid - 72;
        int b = abid & 63, sg = abid >> 6;
        int warp = tid >> 5, lane = tid & 31;
        int wg = sg * 8 + warp;

        if (tid == 0) {
            while (*(volatile int*)&g_qflag < 32) __nanosleep(256);
        }
        __syncthreads();
        __threadfence();

        {
            const float4* qp = (const float4*)g_part;
            float4 s0 = qp[(0 * B + b) * 256 + tid];
            float4 s1 = qp[(1 * B + b) * 256 + tid];
            float4 s2 = qp[(2 * B + b) * 256 + tid];
            float4 s3 = qp[(3 * B + b) * 256 + tid];
            sq[tid] = make_float4(s0.x + s1.x + s2.x + s3.x,
                                  s0.y + s1.y + s2.y + s3.y,
                                  s0.z + s1.z + s2.z + s3.z,
                                  s0.w + s1.w + s2.w + s3.w);
        }
        __syncthreads();

        float4 av[8];
#pragma unroll
        for (int j = 0; j < 8; j++) av[j] = make_float4(0.f, 0.f, 0.f, 0.f);
        float m = -1e30f, l = 0.f;

        int s0r = wg * 32;
        for (int r = 0; r < 32; r++) {
            const float4* row = (const float4*)(enc + ((size_t)(s0r + r) * B + b) * HDIM);
            float4 e[8];
#pragma unroll
            for (int j = 0; j < 8; j++) e[j] = row[j * 32 + lane];
            float d = 0.f;
#pragma unroll
            for (int j = 0; j < 8; j++) {
                float4 q = sq[j * 32 + lane];
                d += e[j].x * q.x + e[j].y * q.y + e[j].z * q.z + e[j].w * q.w;
            }
#pragma unroll
            for (int off = 16; off > 0; off >>= 1)
                d += __shfl_xor_sync(0xffffffffu, d, off);

            float mn  = fmaxf(m, d);
            float fac = __expf(m - mn);
            float p   = __expf(d - mn);
            l = l * fac + p;
            m = mn;
#pragma unroll
            for (int j = 0; j < 8; j++) {
                av[j].x = av[j].x * fac + p * e[j].x;
                av[j].y = av[j].y * fac + p * e[j].y;
                av[j].z = av[j].z * fac + p * e[j].z;
                av[j].w = av[j].w * fac + p * e[j].w;
            }
        }
        int pi = b * 64 + wg;
        if (lane == 0) { g_pm[pi] = m; g_pl[pi] = l; }
        float4* pa = (float4*)(g_pacc + (size_t)pi * HDIM);
#pragma unroll
        for (int j = 0; j < 8; j++) pa[j * 32 + lane] = av[j];
    }
}

// ================= k_post: persistent mid-chain =================
__global__ __launch_bounds__(256) void k_post(
    const float* __restrict__ W_out, const float* __restrict__ W_ih,
    const float* __restrict__ c0, float* __restrict__ out)
{
    extern __shared__ char sm[];
    int u = blockIdx.x, tid = threadIdx.x;
    int nb = gridDim.x;

    if (u == 0 && tid == 0) g_qflag = 0;

    // P1: context combine
    if (u < 64) {
        int b = u, t = tid;
        float M = -1e30f;
        for (int c = 0; c < 64; c++) M = fmaxf(M, g_pm[b * 64 + c]);
        float lsum = 0.f;
        float4 ctx = make_float4(0.f, 0.f, 0.f, 0.f);
        for (int c = 0; c < 64; c++) {
            float fac = __expf(g_pm[b * 64 + c] - M);
            lsum += fac * g_pl[b * 64 + c];
            float4 a = *(const float4*)(g_pacc + (size_t)(b * 64 + c) * HDIM + t * 4);
            ctx.x += fac * a.x; ctx.y += fac * a.y;
            ctx.z += fac * a.z; ctx.w += fac * a.w;
        }
        float inv = 1.f / lsum;
        *(float4*)&g_ctxc[b * HDIM + t * 4] =
            make_float4(ctx.x * inv, ctx.y * inv, ctx.z * inv, ctx.w * inv);
    }
    gridbar(nb);

    // P2: ctx GEMM
    if (u < 128) {
        int tile = u >> 3, slice = u & 7;
        gemm_unit<false>(g_ctxc, HDIM, W_out, 2 * HDIM,
                         tile * 64, slice * 2, slice * 2 + 2, HDIM,
                         g_part + CTX_OFF + (size_t)slice * B * HDIM, 0, nullptr, sm);
    }
    gridbar(nb);

    // P3: combine + tanh
    for (int i = u * 256 + tid; i < B * HDIM; i += nb * 256) {
        int b = i >> 10, n = i & 1023;
        float v = g_pctx[i];
#pragma unroll
        for (int s = 0; s < 8; s++) v += g_part[CTX_OFF + ((size_t)s * B + b) * HDIM + n];
        g_ctxh[i] = tanhf(v);
    }
    gridbar(nb);

    // P4: gates GEMM
    if (u < 128) {
        int tile = u >> 1, slice = u & 1;
        gemm_unit<false>(g_ctxh, HDIM, W_ih, KCAT,
                         tile * 64, slice * 8, slice * 8 + 8, G4,
                         g_part + GATES_OFF + (size_t)slice * B * G4, 0, nullptr, sm);
    }
    gridbar(nb);

    // P5: gates combine + LSTM; write hN as bf16 hi/lo for logits
    for (int i = u * 256 + tid; i < B * HDIM; i += nb * 256) {
        int b = i >> 10, h = i & 1023;
        const float* pg = g_pgates + (size_t)b * G4;
        float gi = pg[h], gf = pg[HDIM + h], gg = pg[2 * HDIM + h], go = pg[3 * HDIM + h];
#pragma unroll
        for (int s = 0; s < 2; s++) {
            const float* p = g_part + GATES_OFF + ((size_t)s * B + b) * (size_t)G4;
            gi += p[h]; gf += p[HDIM + h]; gg += p[2 * HDIM + h]; go += p[3 * HDIM + h];
        }
        float si = 1.f / (1.f + __expf(-gi));
        float sf = 1.f / (1.f + __expf(-gf));
        float so = 1.f / (1.f + __expf(-go));
        float cn = sf * c0[i] + si * tanhf(gg);
        float hn = so * tanhf(cn);
        uint32_t u32 = __float_as_uint(hn);
        uint32_t hi = u32 & 0xFFFF0000u;
        g_hNh[i] = __ushort_as_bfloat16((unsigned short)(u32 >> 16));
        g_hNl[i] = __float2bfloat16(hn - __uint_as_float(hi));
        out[(size_t)B * VDIM + i] = hn;
        out[(size_t)B * VDIM + (size_t)B * HDIM + i] = cn;
    }
}

// ================= k_logits: deep-pipelined bf16 GEMM =================
// smem: A bf16 2x16K @0,16384 (hi +0, lo +8192); W raw 2x16K @32768,49152;
//       W bf16 2x16K @65536,81920 (hi +0, lo +8192). Total 96KB.
__global__ __launch_bounds__(256, 2) void k_logits(
    const float* __restrict__ W, const float* __restrict__ bias,
    float* __restrict__ out)
{
    extern __shared__ char sm[];
    int tid = threadIdx.x, wid = tid >> 5, lane = tid & 31;
    int g = lane >> 2, tig = lane & 3;
    int mbase = (wid >> 1) * 16, nbase = (wid & 1) * 32;
    int n0 = blockIdx.x * 64;
    uint32_t smb = (uint32_t)__cvta_generic_to_shared(sm);
    int frow = tid >> 2, fq = tid & 3;

    int la = lane & 7, lb3 = (lane >> 3) & 1, lb4 = (lane >> 4) & 1;
    uint32_t rawA  = (uint32_t)(mbase + la + lb3 * 8) * 128 + (uint32_t)lb4 * 16;
    uint32_t xorA  = (rawA >> 3) & 0x70;
    uint32_t rawB0 = (uint32_t)(nbase + la + lb4 * 8) * 128 + (uint32_t)lb3 * 16;
    uint32_t rawB1 = rawB0 + 2048;
    uint32_t xorB0 = (rawB0 >> 3) & 0x70;
    uint32_t xorB1 = (rawB1 >> 3) & 0x70;
    uint32_t so0 = swzf((uint32_t)frow * 128 + (uint32_t)fq * 32);
    uint32_t so1 = so0 ^ 16;

    const __nv_bfloat16* Ah;
    const __nv_bfloat16* Al;
    {   // symbol addresses (device-side)
        Ah = g_hNh; Al = g_hNl;
    }

    float acc[4][4];
#pragma unroll
    for (int nf = 0; nf < 4; nf++)
#pragma unroll
        for (int j = 0; j < 4; j++) acc[nf][j] = 0.f;

    bool rv = (n0 + frow) < VDIM;
    const float* wrow = W + (size_t)(rv ? (n0 + frow) : 0) * HDIM;

    auto issue = [&](int ci) {
        int buf = ci & 1;
        int k0 = ci * 64;
        // A bf16 hi/lo: granules fq and fq+4 (16B = 8 bf16 along k)
        uint32_t abase = smb + (uint32_t)buf * 16384;
#pragma unroll
        for (int h = 0; h < 2; h++) {
            const __nv_bfloat16* src = h ? Al : Ah;
            uint32_t base = abase + (uint32_t)h * 8192;
#pragma unroll
            for (int j = 0; j < 2; j++) {
                int gr = fq + j * 4;
                uint32_t dst = base + swzf((uint32_t)frow * 128 + (uint32_t)gr * 16);
                cpasync16(dst, src + (size_t)frow * HDIM + k0 + gr * 8, 16);
            }
        }
        // W raw fp32: 4 granules per thread
        uint32_t wb = smb + 32768 + (uint32_t)buf * 16384 + (uint32_t)frow * 256;
#pragma unroll
        for (int j = 0; j < 4; j++) {
            int q = fq * 4 + j;
            cpasync16(wb + q * 16, wrow + k0 + q * 4, rv ? 16 : 0);
        }
        asm volatile("cp.async.commit_group;" ::: "memory");
    };

    auto convert = [&](int ci) {
        int buf = ci & 1;
        const float4* r4 = (const float4*)(sm + 32768 + buf * 16384 + frow * 256 + fq * 64);
        float v[16];
        float4 a = r4[0], b4 = r4[1], c4 = r4[2], d4 = r4[3];
        v[0]=a.x; v[1]=a.y; v[2]=a.z; v[3]=a.w;
        v[4]=b4.x; v[5]=b4.y; v[6]=b4.z; v[7]=b4.w;
        v[8]=c4.x; v[9]=c4.y; v[10]=c4.z; v[11]=c4.w;
        v[12]=d4.x; v[13]=d4.y; v[14]=d4.z; v[15]=d4.w;
        uint32_t h[8], l[8];
        cvt16(v, h, l);
        char* d = sm + 65536 + buf * 16384;
        *(uint4*)(d + so0)        = make_uint4(h[0], h[1], h[2], h[3]);
        *(uint4*)(d + so1)        = make_uint4(h[4], h[5], h[6], h[7]);
        *(uint4*)(d + 8192 + so0) = make_uint4(l[0], l[1], l[2], l[3]);
        *(uint4*)(d + 8192 + so1) = make_uint4(l[4], l[5], l[6], l[7]);
    };

    issue(0);
    issue(1);

    for (int ci = 0; ci < 16; ci++) {
        int buf = ci & 1;
        if (ci == 15) asm volatile("cp.async.wait_group 0;" ::: "memory");
        else          asm volatile("cp.async.wait_group 1;" ::: "memory");
        convert(ci);
        __syncthreads();

        uint32_t bfA = smb + (uint32_t)buf * 16384;
        uint32_t bfW = smb + 65536 + (uint32_t)buf * 16384;
#pragma unroll
        for (int ks = 0; ks < 4; ks++) {
            uint32_t kb = (uint32_t)ks * 32;
            uint32_t aA = bfA + ((rawA + kb) ^ xorA);
            uint32_t ah[4], al[4];
            ldsm4(ah[0], ah[1], ah[2], ah[3], aA);
            ldsm4(al[0], al[1], al[2], al[3], aA + 8192);
            uint32_t b0 = bfW + ((rawB0 + kb) ^ xorB0);
            uint32_t b1 = bfW + ((rawB1 + kb) ^ xorB1);
            uint32_t bh[8], bl[8];
            ldsm4(bh[0], bh[1], bh[2], bh[3], b0);
            ldsm4(bh[4], bh[5], bh[6], bh[7], b1);
            ldsm4(bl[0], bl[1], bl[2], bl[3], b0 + 8192);
            ldsm4(bl[4], bl[5], bl[6], bl[7], b1 + 8192);
#pragma unroll
            for (int nf = 0; nf < 4; nf++) {
                hmma(acc[nf], ah, &bh[nf * 2]);
                hmma(acc[nf], ah, &bl[nf * 2]);
                hmma(acc[nf], al, &bh[nf * 2]);
            }
        }
        __syncthreads();
        if (ci + 2 < 16) issue(ci + 2);
    }

#pragma unroll
    for (int nf = 0; nf < 4; nf++) {
        int row = mbase + g;
        int n   = n0 + nbase + nf * 8 + tig * 2;
        float2 v0 = make_float2(acc[nf][0], acc[nf][1]);
        float2 v1 = make_float2(acc[nf][2], acc[nf][3]);
        if (n < VDIM) {
            v0.x += bias[n]; v0.y += bias[n + 1];
            v1.x += bias[n]; v1.y += bias[n + 1];
            *(float2*)&out[(size_t)row * VDIM + n]       = v0;
            *(float2*)&out[(size_t)(row + 8) * VDIM + n] = v1;
        }
    }
}

// ---------------- host launch ----------------
extern "C" void kernel_launch(void* const* d_in, const int* in_sizes, int n_in,
                              void* d_out, int out_size)
{
    const int*   tokens = (const int*)  d_in[0];
    const float* enc    = (const float*)d_in[1];
    const float* h0     = (const float*)d_in[2];
    const float* c0     = (const float*)d_in[3];
    const float* emb    = (const float*)d_in[4];
    const float* W_in   = (const float*)d_in[5];
    const float* W_out  = (const float*)d_in[6];
    const float* W_ih   = (const float*)d_in[7];
    const float* W_hh   = (const float*)d_in[8];
    const float* b_ih   = (const float*)d_in[9];
    const float* b_hh   = (const float*)d_in[10];
    const float* W_gen  = (const float*)d_in[11];
    const float* b_gen  = (const float*)d_in[12];
    float* out = (float*)d_out;

    const int SMH = 98304;
    cudaFuncSetAttribute(k_post,   cudaFuncAttributeMaxDynamicSharedMemorySize, SMH);
    cudaFuncSetAttribute(k_logits, cudaFuncAttributeMaxDynamicSharedMemorySize, SMH);

    // 1) mega: 32 q CTAs + 40 indep-GEMM CTAs + 512 attention CTAs
    k_mega<<<584, 256>>>(enc, tokens, emb, h0, W_hh, W_ih, W_out, W_in, b_ih, b_hh);

    // 2) persistent mid-chain: comb -> ctx gemm -> tanh -> gates gemm -> LSTM (+hN bf16 split)
    k_post<<<148, 256, SMH>>>(W_out, W_ih, c0, out);

    // 3) logits = hN @ W_gen^T + b_gen  (deep-pipelined bf16 HMMA)
    k_logits<<<(VDIM + 63) / 64, 256, SMH>>>(W_gen, b_gen, out);
}